// round 3
// baseline (speedup 1.0000x reference)
#include <cuda_runtime.h>
#include <math_constants.h>

#define N_NODES 10000
#define N_EDGES 320000
#define IN_F    512
#define OUT_F   256
#define ALPHA   0.2f

// ---------------- scratch (device globals; no allocation allowed) ----------
__device__ float g_h[(size_t)N_NODES * OUT_F];   // h = x @ W^T + b
__device__ float g_s1[N_NODES];                  // h . a[:256]
__device__ float g_s2[N_NODES];                  // h . a[256:]
__device__ int   g_rowptr[N_NODES + 1];
__device__ int   g_cnt[N_NODES];
__device__ int   g_cur[N_NODES];
__device__ int   g_col[N_EDGES];
__device__ float g_val[N_EDGES];
__device__ float g_colmean[OUT_F];
__device__ int   g_is64;                         // edge_list dtype flag

// ---------------- dtype probe: int64 vs int32 edge_list --------------------
// If int64 (LE, values in [0,1e4)), every odd 32-bit word is a zero high-word.
// With int32 data, odd words are random node ids; P(64 all zero) ~ 1e-128.
__global__ void detect_kernel(const int* __restrict__ p) {
    int nz = 0;
#pragma unroll
    for (int i = 0; i < 64; i++) nz |= p[2 * i + 1];
    g_is64 = (nz == 0) ? 1 : 0;
}

__device__ __forceinline__ int edge_at(const void* el, int idx) {
    int v;
    if (g_is64) v = (int)((const long long*)el)[idx];
    else        v = ((const int*)el)[idx];
    // defensive clamp: never crash on a wrong decode
    return (v < 0) ? 0 : (v >= N_NODES ? N_NODES - 1 : v);
}

// ---------------- init: zero counters ----------------
__global__ void init_kernel() {
    int i = blockIdx.x * blockDim.x + threadIdx.x;
    if (i < N_NODES) { g_cnt[i] = 0; g_cur[i] = 0; }
    if (i < OUT_F)   { g_colmean[i] = 0.f; }
}

// ---------------- SGEMM: h[m][n] = sum_k x[m][k] * W[n][k] + b[n] ----------
#define BM 128
#define BN 128
#define BK 8
#define TM 8
#define TN 8

__global__ void __launch_bounds__(256) gemm_kernel(const float* __restrict__ X,
                                                   const float* __restrict__ W,
                                                   const float* __restrict__ bias) {
    __shared__ float As[BK][BM + 4];
    __shared__ float Bs[BK][BN + 4];

    const int bm  = blockIdx.x * BM;
    const int bn  = blockIdx.y * BN;
    const int tid = threadIdx.x;
    const int tx  = tid % (BN / TN);   // 0..15
    const int ty  = tid / (BN / TN);   // 0..15

    float acc[TM][TN];
#pragma unroll
    for (int i = 0; i < TM; i++)
#pragma unroll
        for (int j = 0; j < TN; j++) acc[i][j] = 0.f;

    const int aRow = tid >> 1;          // 0..127
    const int aCol = (tid & 1) * 4;     // 0 or 4
    const int gr   = bm + aRow;
    const bool aValid = (gr < N_NODES);
    const float* xp = X + (size_t)(aValid ? gr : 0) * IN_F + aCol;
    const float* wp = W + (size_t)(bn + aRow) * IN_F + aCol;   // bn+aRow < 256 always

    for (int k0 = 0; k0 < IN_F; k0 += BK) {
        float4 av = aValid ? *(const float4*)(xp + k0) : make_float4(0.f, 0.f, 0.f, 0.f);
        float4 bv = *(const float4*)(wp + k0);
        As[aCol + 0][aRow] = av.x; As[aCol + 1][aRow] = av.y;
        As[aCol + 2][aRow] = av.z; As[aCol + 3][aRow] = av.w;
        Bs[aCol + 0][aRow] = bv.x; Bs[aCol + 1][aRow] = bv.y;
        Bs[aCol + 2][aRow] = bv.z; Bs[aCol + 3][aRow] = bv.w;
        __syncthreads();

#pragma unroll
        for (int kk = 0; kk < BK; kk++) {
            float ar[TM], br[TN];
#pragma unroll
            for (int i = 0; i < TM; i++) ar[i] = As[kk][ty * TM + i];
#pragma unroll
            for (int j = 0; j < TN; j++) br[j] = Bs[kk][tx * TN + j];
#pragma unroll
            for (int i = 0; i < TM; i++)
#pragma unroll
                for (int j = 0; j < TN; j++) acc[i][j] += ar[i] * br[j];
        }
        __syncthreads();
    }

#pragma unroll
    for (int i = 0; i < TM; i++) {
        int row = bm + ty * TM + i;
        if (row < N_NODES) {
#pragma unroll
            for (int j = 0; j < TN; j += 4) {
                int cn = bn + tx * TN + j;
                float4 o;
                o.x = acc[i][j + 0] + bias[cn + 0];
                o.y = acc[i][j + 1] + bias[cn + 1];
                o.z = acc[i][j + 2] + bias[cn + 2];
                o.w = acc[i][j + 3] + bias[cn + 3];
                *(float4*)(g_h + (size_t)row * OUT_F + cn) = o;
            }
        }
    }
}

// ---------------- s1/s2: per-row dots with attention vector ----------------
__global__ void s_kernel(const float* __restrict__ a) {
    int row = blockIdx.x * blockDim.y + threadIdx.y;
    if (row >= N_NODES) return;
    int lane = threadIdx.x;
    const float* hp = g_h + (size_t)row * OUT_F;
    float p1 = 0.f, p2 = 0.f;
#pragma unroll
    for (int c = lane; c < OUT_F; c += 32) {
        float hv = hp[c];
        p1 += hv * a[c];
        p2 += hv * a[OUT_F + c];
    }
#pragma unroll
    for (int o = 16; o; o >>= 1) {
        p1 += __shfl_xor_sync(0xffffffffu, p1, o);
        p2 += __shfl_xor_sync(0xffffffffu, p2, o);
    }
    if (lane == 0) { g_s1[row] = p1; g_s2[row] = p2; }
}

// ---------------- column means of h (for empty-row fallback) ---------------
__global__ void colmean_kernel() {
    int c = threadIdx.x;
    float acc = 0.f;
    for (int r = blockIdx.x; r < N_NODES; r += gridDim.x)
        acc += g_h[(size_t)r * OUT_F + c];
    atomicAdd(&g_colmean[c], acc);
}

// ---------------- CSR build ------------------------------------------------
__global__ void count_kernel(const void* __restrict__ el) {
    int e = blockIdx.x * blockDim.x + threadIdx.x;
    if (e < N_EDGES) atomicAdd(&g_cnt[edge_at(el, e)], 1);
}

__global__ void scan_kernel() {
    __shared__ int ss[1024];
    int t = threadIdx.x;
    const int CH = (N_NODES + 1023) / 1024;  // 10
    int base = t * CH;
    int s = 0;
    for (int i = 0; i < CH; i++) {
        int idx = base + i;
        if (idx < N_NODES) s += g_cnt[idx];
    }
    ss[t] = s;
    __syncthreads();
    for (int off = 1; off < 1024; off <<= 1) {
        int v = (t >= off) ? ss[t - off] : 0;
        __syncthreads();
        ss[t] += v;
        __syncthreads();
    }
    int run = ss[t] - s;  // exclusive prefix
    for (int i = 0; i < CH; i++) {
        int idx = base + i;
        if (idx < N_NODES) { g_rowptr[idx] = run; run += g_cnt[idx]; }
    }
    if (t == 1023) g_rowptr[N_NODES] = run;
}

__global__ void fill_kernel(const void* __restrict__ el) {
    int e = blockIdx.x * blockDim.x + threadIdx.x;
    if (e >= N_EDGES) return;
    int s = edge_at(el, e);
    int t = edge_at(el, N_EDGES + e);
    float sc = g_s1[s] + g_s2[t];
    float v  = sc > 0.f ? sc : ALPHA * sc;  // leaky_relu per edge BEFORE scatter-add
    int pos = g_rowptr[s] + atomicAdd(&g_cur[s], 1);
    if (pos < N_EDGES) {
        g_col[pos] = t;
        g_val[pos] = v;
    }
}

// ---------------- per-row: dedup + softmax + weighted aggregation ----------
#define MAXK 512

__global__ void __launch_bounds__(256) row_kernel(float* __restrict__ out) {
    int row = blockIdx.x;
    int tid = threadIdx.x;
    int beg = g_rowptr[row];
    int k   = g_rowptr[row + 1] - beg;

    if (k == 0) {  // all-NEG_BIG row: softmax uniform -> mean of h columns
        out[(size_t)row * OUT_F + tid] = g_colmean[tid] * (1.0f / N_NODES);
        return;
    }
    if (k > MAXK) k = MAXK;  // cannot trigger for Poisson(32) rows; safety

    __shared__ int   scol[MAXK];
    __shared__ float sval[MAXK];
    __shared__ float sw[MAXK];
    __shared__ float red[8];
    __shared__ float sM, sZ;

    for (int t = tid; t < k; t += 256) {
        scol[t] = g_col[beg + t];
        sval[t] = g_val[beg + t];
    }
    __syncthreads();

    // Dedup: first occurrence of a tgt owns the entry and sums duplicates
    // (scatter-add of leaky scores at coincident (src,tgt) cells).
    for (int t = tid; t < k; t += 256) {
        int c = scol[t];
        bool owner = true;
        for (int j = 0; j < t; j++)
            if (scol[j] == c) { owner = false; break; }
        float v;
        if (owner) {
            v = sval[t];
            for (int j = t + 1; j < k; j++)
                if (scol[j] == c) v += sval[j];
        } else {
            v = -CUDART_INF_F;  // exp -> 0, drops out of softmax
        }
        sw[t] = v;
    }
    __syncthreads();

    // block max
    float lm = -CUDART_INF_F;
    for (int t = tid; t < k; t += 256) lm = fmaxf(lm, sw[t]);
#pragma unroll
    for (int o = 16; o; o >>= 1) lm = fmaxf(lm, __shfl_xor_sync(0xffffffffu, lm, o));
    if ((tid & 31) == 0) red[tid >> 5] = lm;
    __syncthreads();
    if (tid == 0) {
        float m = red[0];
#pragma unroll
        for (int i = 1; i < 8; i++) m = fmaxf(m, red[i]);
        sM = m;
    }
    __syncthreads();
    float m = sM;

    // exp + block sum
    float ls = 0.f;
    for (int t = tid; t < k; t += 256) {
        float e = __expf(sw[t] - m);
        sw[t] = e;
        ls += e;
    }
#pragma unroll
    for (int o = 16; o; o >>= 1) ls += __shfl_xor_sync(0xffffffffu, ls, o);
    if ((tid & 31) == 0) red[tid >> 5] = ls;
    __syncthreads();
    if (tid == 0) {
        float z = 0.f;
#pragma unroll
        for (int i = 0; i < 8; i++) z += red[i];
        sZ = z;
    }
    __syncthreads();
    float invZ = 1.0f / sZ;

    // weighted aggregation: thread = output column, loop over row's edges.
    float acc = 0.f;
    for (int t = 0; t < k; t++)
        acc += sw[t] * g_h[(size_t)scol[t] * OUT_F + tid];

    out[(size_t)row * OUT_F + tid] = acc * invZ;
}

// ---------------- launch ---------------------------------------------------
extern "C" void kernel_launch(void* const* d_in, const int* in_sizes, int n_in,
                              void* d_out, int out_size) {
    const float* x  = (const float*)d_in[0];
    const float* W  = (const float*)d_in[1];
    const float* b  = (const float*)d_in[2];
    const float* a  = (const float*)d_in[3];
    const void*  el = d_in[4];
    float* out = (float*)d_out;

    detect_kernel<<<1, 1>>>((const int*)el);
    init_kernel<<<(N_NODES + 255) / 256, 256>>>();

    dim3 ggrid((N_NODES + BM - 1) / BM, OUT_F / BN);
    gemm_kernel<<<ggrid, 256>>>(x, W, b);

    s_kernel<<<(N_NODES + 7) / 8, dim3(32, 8)>>>(a);
    colmean_kernel<<<128, OUT_F>>>();

    count_kernel<<<(N_EDGES + 255) / 256, 256>>>(el);
    scan_kernel<<<1, 1024>>>();
    fill_kernel<<<(N_EDGES + 255) / 256, 256>>>(el);

    row_kernel<<<N_NODES, 256>>>(out);
}

// round 5
// speedup vs baseline: 1.3136x; 1.3136x over previous
#include <cuda_runtime.h>
#include <cuda_bf16.h>
#include <math_constants.h>
#include <cstdint>

#define N_NODES 10000
#define N_EDGES 320000
#define IN_F    512
#define OUT_F   256
#define ALPHA   0.2f

// ---------------- scratch (device globals; no allocation allowed) ----------
__device__ float g_h[(size_t)N_NODES * OUT_F];
__device__ float g_s1[N_NODES];
__device__ float g_s2[N_NODES];
__device__ int   g_rowptr[N_NODES + 1];
__device__ int   g_cnt[N_NODES];
__device__ int   g_cur[N_NODES];
__device__ int   g_col[N_EDGES];
__device__ float g_val[N_EDGES];
__device__ float g_colmean[OUT_F];
__device__ int   g_is64;
__device__ __nv_bfloat16 g_xh[(size_t)N_NODES * IN_F];
__device__ __nv_bfloat16 g_xl[(size_t)N_NODES * IN_F];
__device__ __nv_bfloat16 g_wh[(size_t)OUT_F * IN_F];
__device__ __nv_bfloat16 g_wl[(size_t)OUT_F * IN_F];

// ---------------- small helpers --------------------------------------------
__device__ __forceinline__ void ldsm4(uint32_t* r, uint32_t addr) {
    asm volatile("ldmatrix.sync.aligned.m8n8.x4.shared.b16 {%0,%1,%2,%3}, [%4];"
                 : "=r"(r[0]), "=r"(r[1]), "=r"(r[2]), "=r"(r[3]) : "r"(addr));
}
__device__ __forceinline__ void mma16816(float* c, const uint32_t* A, uint32_t b0, uint32_t b1) {
    asm volatile("mma.sync.aligned.m16n8k16.row.col.f32.bf16.bf16.f32 "
                 "{%0,%1,%2,%3}, {%4,%5,%6,%7}, {%8,%9}, {%0,%1,%2,%3};"
                 : "+f"(c[0]), "+f"(c[1]), "+f"(c[2]), "+f"(c[3])
                 : "r"(A[0]), "r"(A[1]), "r"(A[2]), "r"(A[3]), "r"(b0), "r"(b1));
}

// ---------------- dtype probe (int64 vs int32 edge_list) -------------------
__global__ void detect_kernel(const int* __restrict__ p) {
    int nz = 0;
#pragma unroll
    for (int i = 0; i < 64; i++) nz |= p[2 * i + 1];
    g_is64 = (nz == 0) ? 1 : 0;
}
__device__ __forceinline__ int edge_at(const void* el, int idx) {
    int v;
    if (g_is64) v = (int)((const long long*)el)[idx];
    else        v = ((const int*)el)[idx];
    return (v < 0) ? 0 : (v >= N_NODES ? N_NODES - 1 : v);
}

__global__ void init_kernel() {
    int i = blockIdx.x * blockDim.x + threadIdx.x;
    if (i < N_NODES) { g_cnt[i] = 0; g_cur[i] = 0; g_s1[i] = 0.f; g_s2[i] = 0.f; }
    if (i < OUT_F)   { g_colmean[i] = 0.f; }
}

// ---------------- fp32 -> bf16 hi/lo split ---------------------------------
__global__ void cvt_kernel(const float* __restrict__ src,
                           __nv_bfloat16* __restrict__ hi,
                           __nv_bfloat16* __restrict__ lo, int n4) {
    int i = blockIdx.x * blockDim.x + threadIdx.x;
    if (i >= n4) return;
    float4 v = ((const float4*)src)[i];
    __nv_bfloat16 h0 = __float2bfloat16_rn(v.x), h1 = __float2bfloat16_rn(v.y);
    __nv_bfloat16 h2 = __float2bfloat16_rn(v.z), h3 = __float2bfloat16_rn(v.w);
    __nv_bfloat162 H0 = {h0, h1}, H1 = {h2, h3};
    __nv_bfloat162 L0 = {__float2bfloat16_rn(v.x - __bfloat162float(h0)),
                         __float2bfloat16_rn(v.y - __bfloat162float(h1))};
    __nv_bfloat162 L1 = {__float2bfloat16_rn(v.z - __bfloat162float(h2)),
                         __float2bfloat16_rn(v.w - __bfloat162float(h3))};
    ((__nv_bfloat162*)hi)[2 * i]     = H0;
    ((__nv_bfloat162*)hi)[2 * i + 1] = H1;
    ((__nv_bfloat162*)lo)[2 * i]     = L0;
    ((__nv_bfloat162*)lo)[2 * i + 1] = L1;
}

// ---------------- tensor-core GEMM (mma.sync bf16, hi/lo split) ------------
// CTA tile 128x128, K chunks of 32. 8 warps = 4(M) x 2(N); warp tile 32x64.
#define BM 128
#define BN 128
#define KB 32
#define KST 40   // smem row stride in bf16 (conflict-free for ldmatrix)

__global__ void __launch_bounds__(256, 2) gemm_mma_kernel(
    const float* __restrict__ bias, const float* __restrict__ av)
{
    __shared__ __nv_bfloat16 sAh[BM * KST], sAl[BM * KST];
    __shared__ __nv_bfloat16 sBh[BN * KST], sBl[BN * KST];

    const int tid  = threadIdx.x;
    const int lane = tid & 31;
    const int wid  = tid >> 5;
    const int wm   = wid & 3;       // warp M index (0..3)
    const int wn   = wid >> 2;      // warp N index (0..1)
    const int bm   = blockIdx.x * BM;
    const int bn   = blockIdx.y * BN;

    float acc[2][8][4];
#pragma unroll
    for (int i = 0; i < 2; i++)
#pragma unroll
        for (int j = 0; j < 8; j++)
#pragma unroll
            for (int q = 0; q < 4; q++) acc[i][j][q] = 0.f;

    // staging: thread -> (row, 16-col half)
    const int sr = tid >> 1;
    const int sh = (tid & 1) * 16;
    const bool avalid = (bm + sr < N_NODES);
    const size_t xoff = (size_t)(avalid ? bm + sr : 0) * IN_F + sh;
    const size_t woff = (size_t)(bn + sr) * IN_F + sh;
    const uint32_t sAh_b = (uint32_t)__cvta_generic_to_shared(sAh);
    const uint32_t sAl_b = (uint32_t)__cvta_generic_to_shared(sAl);
    const uint32_t sBh_b = (uint32_t)__cvta_generic_to_shared(sBh);
    const uint32_t sBl_b = (uint32_t)__cvta_generic_to_shared(sBl);
    const uint32_t sdst  = (uint32_t)(sr * KST + sh) * 2;

    // ldmatrix lane address components
    const uint32_t a_row = lane & 15, a_cb = (lane >> 4) * 8;
    const uint32_t b_row = (lane & 7) + ((lane & 16) ? 8 : 0);
    const uint32_t b_cb  = (lane & 8) ? 8 : 0;

    for (int ch = 0; ch < IN_F / KB; ch++) {
        const int k0 = ch * KB;
        // ---- stage chunk ----
        uint4 xh0 = avalid ? *(const uint4*)(g_xh + xoff + k0)     : make_uint4(0,0,0,0);
        uint4 xh1 = avalid ? *(const uint4*)(g_xh + xoff + k0 + 8) : make_uint4(0,0,0,0);
        uint4 xl0 = avalid ? *(const uint4*)(g_xl + xoff + k0)     : make_uint4(0,0,0,0);
        uint4 xl1 = avalid ? *(const uint4*)(g_xl + xoff + k0 + 8) : make_uint4(0,0,0,0);
        uint4 wh0 = *(const uint4*)(g_wh + woff + k0);
        uint4 wh1 = *(const uint4*)(g_wh + woff + k0 + 8);
        uint4 wl0 = *(const uint4*)(g_wl + woff + k0);
        uint4 wl1 = *(const uint4*)(g_wl + woff + k0 + 8);
        __syncthreads();   // previous chunk fully consumed
        *(uint4*)((char*)sAh + sdst)      = xh0;
        *(uint4*)((char*)sAh + sdst + 16) = xh1;
        *(uint4*)((char*)sAl + sdst)      = xl0;
        *(uint4*)((char*)sAl + sdst + 16) = xl1;
        *(uint4*)((char*)sBh + sdst)      = wh0;
        *(uint4*)((char*)sBh + sdst + 16) = wh1;
        *(uint4*)((char*)sBl + sdst)      = wl0;
        *(uint4*)((char*)sBl + sdst + 16) = wl1;
        __syncthreads();

        // ---- compute: 2 k16 steps ----
#pragma unroll
        for (int ks = 0; ks < KB; ks += 16) {
            uint32_t ah[2][4], al[2][4];
#pragma unroll
            for (int mi = 0; mi < 2; mi++) {
                uint32_t off = ((wm * 32 + mi * 16 + a_row) * KST + ks + a_cb) * 2;
                ldsm4(ah[mi], sAh_b + off);
                ldsm4(al[mi], sAl_b + off);
            }
#pragma unroll
            for (int g = 0; g < 4; g++) {
                uint32_t off = ((wn * 64 + g * 16 + b_row) * KST + ks + b_cb) * 2;
                uint32_t bh[4], bl[4];
                ldsm4(bh, sBh_b + off);
                ldsm4(bl, sBl_b + off);
#pragma unroll
                for (int mi = 0; mi < 2; mi++) {
                    mma16816(acc[mi][2 * g],     ah[mi], bh[0], bh[1]);
                    mma16816(acc[mi][2 * g + 1], ah[mi], bh[2], bh[3]);
                    mma16816(acc[mi][2 * g],     ah[mi], bl[0], bl[1]);
                    mma16816(acc[mi][2 * g + 1], ah[mi], bl[2], bl[3]);
                    mma16816(acc[mi][2 * g],     al[mi], bh[0], bh[1]);
                    mma16816(acc[mi][2 * g + 1], al[mi], bh[2], bh[3]);
                }
            }
        }
    }

    // ---- epilogue: bias, store h, fused s1/s2 partials ----
    const int q  = lane >> 2;    // row within 8-group
    const int qt = lane & 3;     // col pair selector
#pragma unroll
    for (int mi = 0; mi < 2; mi++) {
#pragma unroll
        for (int half = 0; half < 2; half++) {
            int row = bm + wm * 32 + mi * 16 + half * 8 + q;
            bool vr = (row < N_NODES);
            float p1 = 0.f, p2 = 0.f;
#pragma unroll
            for (int ni = 0; ni < 8; ni++) {
                int col = bn + wn * 64 + ni * 8 + qt * 2;
                float v0 = acc[mi][ni][half * 2 + 0] + bias[col];
                float v1 = acc[mi][ni][half * 2 + 1] + bias[col + 1];
                if (vr) *(float2*)(g_h + (size_t)row * OUT_F + col) = make_float2(v0, v1);
                p1 += v0 * av[col]         + v1 * av[col + 1];
                p2 += v0 * av[OUT_F + col] + v1 * av[OUT_F + col + 1];
            }
            p1 += __shfl_xor_sync(0xffffffffu, p1, 1);
            p1 += __shfl_xor_sync(0xffffffffu, p1, 2);
            p2 += __shfl_xor_sync(0xffffffffu, p2, 1);
            p2 += __shfl_xor_sync(0xffffffffu, p2, 2);
            if (qt == 0 && vr) {
                atomicAdd(&g_s1[row], p1);
                atomicAdd(&g_s2[row], p2);
            }
        }
    }
}

// ---------------- column means (empty-row fallback) ------------------------
__global__ void colmean_kernel() {
    int c = threadIdx.x;
    float acc = 0.f;
    for (int r = blockIdx.x; r < N_NODES; r += gridDim.x)
        acc += g_h[(size_t)r * OUT_F + c];
    atomicAdd(&g_colmean[c], acc);
}

// ---------------- CSR build ------------------------------------------------
__global__ void count_kernel(const void* __restrict__ el) {
    int e = blockIdx.x * blockDim.x + threadIdx.x;
    if (e < N_EDGES) atomicAdd(&g_cnt[edge_at(el, e)], 1);
}

__global__ void scan_kernel() {
    __shared__ int ss[1024];
    int t = threadIdx.x;
    const int CH = (N_NODES + 1023) / 1024;
    int base = t * CH;
    int s = 0;
    for (int i = 0; i < CH; i++) {
        int idx = base + i;
        if (idx < N_NODES) s += g_cnt[idx];
    }
    ss[t] = s;
    __syncthreads();
    for (int off = 1; off < 1024; off <<= 1) {
        int v = (t >= off) ? ss[t - off] : 0;
        __syncthreads();
        ss[t] += v;
        __syncthreads();
    }
    int run = ss[t] - s;
    for (int i = 0; i < CH; i++) {
        int idx = base + i;
        if (idx < N_NODES) { g_rowptr[idx] = run; run += g_cnt[idx]; }
    }
    if (t == 1023) g_rowptr[N_NODES] = run;
}

__global__ void fill_kernel(const void* __restrict__ el) {
    int e = blockIdx.x * blockDim.x + threadIdx.x;
    if (e >= N_EDGES) return;
    int s = edge_at(el, e);
    int t = edge_at(el, N_EDGES + e);
    float sc = g_s1[s] + g_s2[t];
    float v  = sc > 0.f ? sc : ALPHA * sc;
    int pos = g_rowptr[s] + atomicAdd(&g_cur[s], 1);
    if (pos < N_EDGES) { g_col[pos] = t; g_val[pos] = v; }
}

// ---------------- per-row: dedup + softmax + aggregation -------------------
#define MAXK 512

__global__ void __launch_bounds__(256) row_kernel(float* __restrict__ out) {
    int row = blockIdx.x;
    int tid = threadIdx.x;
    int beg = g_rowptr[row];
    int k   = g_rowptr[row + 1] - beg;

    if (k == 0) {
        out[(size_t)row * OUT_F + tid] = g_colmean[tid] * (1.0f / N_NODES);
        return;
    }
    if (k > MAXK) k = MAXK;

    __shared__ int   scol[MAXK];
    __shared__ float sval[MAXK];
    __shared__ float sw[MAXK];
    __shared__ float red[8];
    __shared__ float sM, sZ;

    for (int t = tid; t < k; t += 256) {
        scol[t] = g_col[beg + t];
        sval[t] = g_val[beg + t];
    }
    __syncthreads();

    for (int t = tid; t < k; t += 256) {
        int c = scol[t];
        bool owner = true;
        for (int j = 0; j < t; j++)
            if (scol[j] == c) { owner = false; break; }
        float v;
        if (owner) {
            v = sval[t];
            for (int j = t + 1; j < k; j++)
                if (scol[j] == c) v += sval[j];
        } else {
            v = -CUDART_INF_F;
        }
        sw[t] = v;
    }
    __syncthreads();

    float lm = -CUDART_INF_F;
    for (int t = tid; t < k; t += 256) lm = fmaxf(lm, sw[t]);
#pragma unroll
    for (int o = 16; o; o >>= 1) lm = fmaxf(lm, __shfl_xor_sync(0xffffffffu, lm, o));
    if ((tid & 31) == 0) red[tid >> 5] = lm;
    __syncthreads();
    if (tid == 0) {
        float m = red[0];
#pragma unroll
        for (int i = 1; i < 8; i++) m = fmaxf(m, red[i]);
        sM = m;
    }
    __syncthreads();
    float m = sM;

    float ls = 0.f;
    for (int t = tid; t < k; t += 256) {
        float e = __expf(sw[t] - m);
        sw[t] = e;
        ls += e;
    }
#pragma unroll
    for (int o = 16; o; o >>= 1) ls += __shfl_xor_sync(0xffffffffu, ls, o);
    if ((tid & 31) == 0) red[tid >> 5] = ls;
    __syncthreads();
    if (tid == 0) {
        float z = 0.f;
#pragma unroll
        for (int i = 0; i < 8; i++) z += red[i];
        sZ = z;
    }
    __syncthreads();
    float invZ = 1.0f / sZ;

    float acc = 0.f;
    int t = 0;
    for (; t + 4 <= k; t += 4) {
        float w0 = sw[t], w1 = sw[t + 1], w2 = sw[t + 2], w3 = sw[t + 3];
        int   c0 = scol[t], c1 = scol[t + 1], c2 = scol[t + 2], c3 = scol[t + 3];
        acc += w0 * g_h[(size_t)c0 * OUT_F + tid];
        acc += w1 * g_h[(size_t)c1 * OUT_F + tid];
        acc += w2 * g_h[(size_t)c2 * OUT_F + tid];
        acc += w3 * g_h[(size_t)c3 * OUT_F + tid];
    }
    for (; t < k; t++) acc += sw[t] * g_h[(size_t)scol[t] * OUT_F + tid];

    out[(size_t)row * OUT_F + tid] = acc * invZ;
}

// ---------------- launch ---------------------------------------------------
extern "C" void kernel_launch(void* const* d_in, const int* in_sizes, int n_in,
                              void* d_out, int out_size) {
    const float* x  = (const float*)d_in[0];
    const float* W  = (const float*)d_in[1];
    const float* b  = (const float*)d_in[2];
    const float* a  = (const float*)d_in[3];
    const void*  el = d_in[4];
    float* out = (float*)d_out;

    detect_kernel<<<1, 1>>>((const int*)el);
    init_kernel<<<(N_NODES + 255) / 256, 256>>>();

    __nv_bfloat16 *xh, *xl, *wh, *wl;
    cudaGetSymbolAddress((void**)&xh, g_xh);
    cudaGetSymbolAddress((void**)&xl, g_xl);
    cudaGetSymbolAddress((void**)&wh, g_wh);
    cudaGetSymbolAddress((void**)&wl, g_wl);

    int nx4 = N_NODES * IN_F / 4;
    int nw4 = OUT_F * IN_F / 4;
    cvt_kernel<<<(nx4 + 255) / 256, 256>>>(x, xh, xl, nx4);
    cvt_kernel<<<(nw4 + 255) / 256, 256>>>(W, wh, wl, nw4);

    dim3 ggrid((N_NODES + BM - 1) / BM, OUT_F / BN);   // (79, 2)
    gemm_mma_kernel<<<ggrid, 256>>>(b, a);

    colmean_kernel<<<128, OUT_F>>>();
    count_kernel<<<(N_EDGES + 255) / 256, 256>>>(el);
    scan_kernel<<<1, 1024>>>();
    fill_kernel<<<(N_EDGES + 255) / 256, 256>>>(el);

    row_kernel<<<N_NODES, 256>>>(out);
}

// round 6
// speedup vs baseline: 1.5049x; 1.1456x over previous
#include <cuda_runtime.h>
#include <cuda_bf16.h>
#include <math_constants.h>
#include <cstdint>

#define N_NODES 10000
#define N_EDGES 320000
#define IN_F    512
#define OUT_F   256
#define ALPHA   0.2f

// ---------------- scratch (device globals; no allocation allowed) ----------
__device__ float g_h[(size_t)N_NODES * OUT_F];
__device__ float g_s1[N_NODES];
__device__ float g_s2[N_NODES];
__device__ int   g_rowptr[N_NODES + 1];
__device__ int   g_cnt[N_NODES];
__device__ int   g_cur[N_NODES];
__device__ int   g_col[N_EDGES];
__device__ float g_val[N_EDGES];
__device__ float g_colmean[OUT_F];
__device__ int   g_is64;
__device__ int   g_hasempty;
__device__ __nv_bfloat16 g_xh[(size_t)N_NODES * IN_F];
__device__ __nv_bfloat16 g_xl[(size_t)N_NODES * IN_F];
__device__ __nv_bfloat16 g_wh[(size_t)OUT_F * IN_F];
__device__ __nv_bfloat16 g_wl[(size_t)OUT_F * IN_F];

// ---------------- small helpers --------------------------------------------
__device__ __forceinline__ void ldsm4(uint32_t* r, uint32_t addr) {
    asm volatile("ldmatrix.sync.aligned.m8n8.x4.shared.b16 {%0,%1,%2,%3}, [%4];"
                 : "=r"(r[0]), "=r"(r[1]), "=r"(r[2]), "=r"(r[3]) : "r"(addr));
}
__device__ __forceinline__ void mma16816(float* c, const uint32_t* A, uint32_t b0, uint32_t b1) {
    asm volatile("mma.sync.aligned.m16n8k16.row.col.f32.bf16.bf16.f32 "
                 "{%0,%1,%2,%3}, {%4,%5,%6,%7}, {%8,%9}, {%0,%1,%2,%3};"
                 : "+f"(c[0]), "+f"(c[1]), "+f"(c[2]), "+f"(c[3])
                 : "r"(A[0]), "r"(A[1]), "r"(A[2]), "r"(A[3]), "r"(b0), "r"(b1));
}
__device__ __forceinline__ void cpa16(uint32_t dst, const void* src) {
    asm volatile("cp.async.cg.shared.global [%0], [%1], 16;" :: "r"(dst), "l"(src));
}

// ---------------- edge decode ----------------------------------------------
__device__ __forceinline__ int edge_at(const void* el, int idx) {
    int v;
    if (g_is64) v = (int)((const long long*)el)[idx];
    else        v = ((const int*)el)[idx];
    return (v < 0) ? 0 : (v >= N_NODES ? N_NODES - 1 : v);
}

// ---------------- init (+ dtype probe in block 0) ---------------------------
__global__ void init_kernel(const int* __restrict__ p) {
    int i = blockIdx.x * blockDim.x + threadIdx.x;
    if (i == 0) {
        int nz = 0;
#pragma unroll
        for (int j = 0; j < 64; j++) nz |= p[2 * j + 1];
        g_is64 = (nz == 0) ? 1 : 0;
        g_hasempty = 0;
    }
    if (i < N_NODES) { g_cnt[i] = 0; g_cur[i] = 0; g_s1[i] = 0.f; g_s2[i] = 0.f; }
    if (i < OUT_F)   { g_colmean[i] = 0.f; }
}

// ---------------- fp32 -> bf16 hi/lo split (X and W in one launch) ---------
__global__ void cvt_kernel(const float* __restrict__ X, const float* __restrict__ W) {
    const int nx4 = N_NODES * IN_F / 4;
    const int nw4 = OUT_F * IN_F / 4;
    int i = blockIdx.x * blockDim.x + threadIdx.x;
    if (i >= nx4 + nw4) return;
    const float* src;
    __nv_bfloat16 *hi, *lo;
    int j;
    if (i < nx4) { src = X; hi = g_xh; lo = g_xl; j = i; }
    else         { src = W; hi = g_wh; lo = g_wl; j = i - nx4; }
    float4 v = ((const float4*)src)[j];
    __nv_bfloat16 h0 = __float2bfloat16_rn(v.x), h1 = __float2bfloat16_rn(v.y);
    __nv_bfloat16 h2 = __float2bfloat16_rn(v.z), h3 = __float2bfloat16_rn(v.w);
    __nv_bfloat162 H0 = {h0, h1}, H1 = {h2, h3};
    __nv_bfloat162 L0 = {__float2bfloat16_rn(v.x - __bfloat162float(h0)),
                         __float2bfloat16_rn(v.y - __bfloat162float(h1))};
    __nv_bfloat162 L1 = {__float2bfloat16_rn(v.z - __bfloat162float(h2)),
                         __float2bfloat16_rn(v.w - __bfloat162float(h3))};
    ((__nv_bfloat162*)hi)[2 * j]     = H0;
    ((__nv_bfloat162*)hi)[2 * j + 1] = H1;
    ((__nv_bfloat162*)lo)[2 * j]     = L0;
    ((__nv_bfloat162*)lo)[2 * j + 1] = L1;
}

// ---------------- tensor-core GEMM, cp.async double-buffered ---------------
// CTA 128x128, K chunks of 32, 8 warps = 4(M) x 2(N), warp tile 32x64.
#define BM 128
#define BN 128
#define KB 32
#define KST 40                     // smem row stride (bf16), ldmatrix conflict-free
#define STG_B (BM * KST * 2)       // bytes per array per stage: 10240
#define NC (IN_F / KB)             // 16
#define SM_GEMM (2 * 4 * STG_B)    // 81920

__global__ void __launch_bounds__(256, 2) gemm_mma_kernel(
    const float* __restrict__ bias, const float* __restrict__ av)
{
    extern __shared__ char dsm[];
    const uint32_t smb = (uint32_t)__cvta_generic_to_shared(dsm);

    const int tid  = threadIdx.x;
    const int lane = tid & 31;
    const int wid  = tid >> 5;
    const int wm   = wid & 3;
    const int wn   = wid >> 2;
    const int bm   = blockIdx.x * BM;
    const int bn   = blockIdx.y * BN;

    float acc[2][8][4];
#pragma unroll
    for (int i = 0; i < 2; i++)
#pragma unroll
        for (int j = 0; j < 8; j++)
#pragma unroll
            for (int q = 0; q < 4; q++) acc[i][j][q] = 0.f;

    // staging mapping: thread -> (row sr, 16-col half sh)
    const int sr = tid >> 1;
    const int sh = (tid & 1) * 16;
    const int rowA = (bm + sr < N_NODES) ? bm + sr : N_NODES - 1;  // clamp: pad rows discarded later
    const __nv_bfloat16* xhp = g_xh + (size_t)rowA * IN_F + sh;
    const __nv_bfloat16* xlp = g_xl + (size_t)rowA * IN_F + sh;
    const __nv_bfloat16* whp = g_wh + (size_t)(bn + sr) * IN_F + sh;
    const __nv_bfloat16* wlp = g_wl + (size_t)(bn + sr) * IN_F + sh;
    const uint32_t sdst = (uint32_t)(sr * KST + sh) * 2;

    // ldmatrix lane address components
    const uint32_t a_row = lane & 15, a_cb = (lane >> 4) * 8;
    const uint32_t b_row = (lane & 7) + ((lane & 16) ? 8 : 0);
    const uint32_t b_cb  = (lane & 8) ? 8 : 0;

#define PREFETCH(ch, st) do {                                     \
    const int _k0 = (ch) * KB;                                    \
    uint32_t _b = smb + (st) * 4 * STG_B + sdst;                  \
    cpa16(_b,                  xhp + _k0);                        \
    cpa16(_b + 16,             xhp + _k0 + 8);                    \
    cpa16(_b + STG_B,          xlp + _k0);                        \
    cpa16(_b + STG_B + 16,     xlp + _k0 + 8);                    \
    cpa16(_b + 2 * STG_B,      whp + _k0);                        \
    cpa16(_b + 2 * STG_B + 16, whp + _k0 + 8);                    \
    cpa16(_b + 3 * STG_B,      wlp + _k0);                        \
    cpa16(_b + 3 * STG_B + 16, wlp + _k0 + 8);                    \
    asm volatile("cp.async.commit_group;" ::: "memory");          \
} while (0)

    PREFETCH(0, 0);

    for (int ch = 0; ch < NC; ch++) {
        if (ch + 1 < NC) {
            PREFETCH(ch + 1, (ch + 1) & 1);
            asm volatile("cp.async.wait_group 1;" ::: "memory");
        } else {
            asm volatile("cp.async.wait_group 0;" ::: "memory");
        }
        __syncthreads();

        const uint32_t sAh_b = smb + (ch & 1) * 4 * STG_B;
        const uint32_t sAl_b = sAh_b + STG_B;
        const uint32_t sBh_b = sAh_b + 2 * STG_B;
        const uint32_t sBl_b = sAh_b + 3 * STG_B;

#pragma unroll
        for (int ks = 0; ks < KB; ks += 16) {
            uint32_t ah[2][4], al[2][4];
#pragma unroll
            for (int mi = 0; mi < 2; mi++) {
                uint32_t off = ((wm * 32 + mi * 16 + a_row) * KST + ks + a_cb) * 2;
                ldsm4(ah[mi], sAh_b + off);
                ldsm4(al[mi], sAl_b + off);
            }
#pragma unroll
            for (int g = 0; g < 4; g++) {
                uint32_t off = ((wn * 64 + g * 16 + b_row) * KST + ks + b_cb) * 2;
                uint32_t bh[4], bl[4];
                ldsm4(bh, sBh_b + off);
                ldsm4(bl, sBl_b + off);
#pragma unroll
                for (int mi = 0; mi < 2; mi++) {
                    mma16816(acc[mi][2 * g],     ah[mi], bh[0], bh[1]);
                    mma16816(acc[mi][2 * g + 1], ah[mi], bh[2], bh[3]);
                    mma16816(acc[mi][2 * g],     ah[mi], bl[0], bl[1]);
                    mma16816(acc[mi][2 * g + 1], ah[mi], bl[2], bl[3]);
                    mma16816(acc[mi][2 * g],     al[mi], bh[0], bh[1]);
                    mma16816(acc[mi][2 * g + 1], al[mi], bh[2], bh[3]);
                }
            }
        }
        __syncthreads();
    }
#undef PREFETCH

    // ---- epilogue: bias, store h, fused s1/s2 partials ----
    const int q  = lane >> 2;
    const int qt = lane & 3;
#pragma unroll
    for (int mi = 0; mi < 2; mi++) {
#pragma unroll
        for (int half = 0; half < 2; half++) {
            int row = bm + wm * 32 + mi * 16 + half * 8 + q;
            bool vr = (row < N_NODES);
            float p1 = 0.f, p2 = 0.f;
#pragma unroll
            for (int ni = 0; ni < 8; ni++) {
                int col = bn + wn * 64 + ni * 8 + qt * 2;
                float v0 = acc[mi][ni][half * 2 + 0] + bias[col];
                float v1 = acc[mi][ni][half * 2 + 1] + bias[col + 1];
                if (vr) *(float2*)(g_h + (size_t)row * OUT_F + col) = make_float2(v0, v1);
                p1 += v0 * av[col]         + v1 * av[col + 1];
                p2 += v0 * av[OUT_F + col] + v1 * av[OUT_F + col + 1];
            }
            p1 += __shfl_xor_sync(0xffffffffu, p1, 1);
            p1 += __shfl_xor_sync(0xffffffffu, p1, 2);
            p2 += __shfl_xor_sync(0xffffffffu, p2, 1);
            p2 += __shfl_xor_sync(0xffffffffu, p2, 2);
            if (qt == 0 && vr) {
                atomicAdd(&g_s1[row], p1);
                atomicAdd(&g_s2[row], p2);
            }
        }
    }
}

// ---------------- column means (only if an empty row exists) ---------------
__global__ void colmean_kernel() {
    if (!g_hasempty) return;
    int c = threadIdx.x;
    float acc = 0.f;
    for (int r = blockIdx.x; r < N_NODES; r += gridDim.x)
        acc += g_h[(size_t)r * OUT_F + c];
    atomicAdd(&g_colmean[c], acc);
}

// ---------------- CSR build ------------------------------------------------
__global__ void count_kernel(const void* __restrict__ el) {
    int e = blockIdx.x * blockDim.x + threadIdx.x;
    if (e < N_EDGES) atomicAdd(&g_cnt[edge_at(el, e)], 1);
}

__global__ void scan_kernel() {
    __shared__ int ss[1024];
    int t = threadIdx.x;
    const int CH = (N_NODES + 1023) / 1024;
    int base = t * CH;
    int s = 0;
    int empty = 0;
    for (int i = 0; i < CH; i++) {
        int idx = base + i;
        if (idx < N_NODES) {
            int c = g_cnt[idx];
            s += c;
            empty |= (c == 0);
        }
    }
    if (empty) g_hasempty = 1;
    ss[t] = s;
    __syncthreads();
    for (int off = 1; off < 1024; off <<= 1) {
        int v = (t >= off) ? ss[t - off] : 0;
        __syncthreads();
        ss[t] += v;
        __syncthreads();
    }
    int run = ss[t] - s;
    for (int i = 0; i < CH; i++) {
        int idx = base + i;
        if (idx < N_NODES) { g_rowptr[idx] = run; run += g_cnt[idx]; }
    }
    if (t == 1023) g_rowptr[N_NODES] = run;
}

__global__ void fill_kernel(const void* __restrict__ el) {
    int e = blockIdx.x * blockDim.x + threadIdx.x;
    if (e >= N_EDGES) return;
    int s = edge_at(el, e);
    int t = edge_at(el, N_EDGES + e);
    float sc = g_s1[s] + g_s2[t];
    float v  = sc > 0.f ? sc : ALPHA * sc;
    int pos = g_rowptr[s] + atomicAdd(&g_cur[s], 1);
    if (pos < N_EDGES) { g_col[pos] = t; g_val[pos] = v; }
}

// ---------------- per-row: dedup + softmax + aggregation -------------------
#define MAXK 512

__global__ void __launch_bounds__(256) row_kernel(float* __restrict__ out) {
    int row = blockIdx.x;
    int tid = threadIdx.x;
    int beg = g_rowptr[row];
    int k   = g_rowptr[row + 1] - beg;

    if (k == 0) {
        out[(size_t)row * OUT_F + tid] = g_colmean[tid] * (1.0f / N_NODES);
        return;
    }
    if (k > MAXK) k = MAXK;

    __shared__ int    scol[MAXK];
    __shared__ float  sval[MAXK];
    __shared__ float  sw[MAXK];
    __shared__ float  red[8];
    __shared__ float  sM, sZ;
    __shared__ float4 sred[4][64];

    for (int t = tid; t < k; t += 256) {
        scol[t] = g_col[beg + t];
        sval[t] = g_val[beg + t];
    }
    __syncthreads();

    // dedup: first occurrence owns and sums duplicates (scatter-add semantics)
    for (int t = tid; t < k; t += 256) {
        int c = scol[t];
        bool owner = true;
        for (int j = 0; j < t; j++)
            if (scol[j] == c) { owner = false; break; }
        float v;
        if (owner) {
            v = sval[t];
            for (int j = t + 1; j < k; j++)
                if (scol[j] == c) v += sval[j];
        } else {
            v = -CUDART_INF_F;
        }
        sw[t] = v;
    }
    __syncthreads();

    float lm = -CUDART_INF_F;
    for (int t = tid; t < k; t += 256) lm = fmaxf(lm, sw[t]);
#pragma unroll
    for (int o = 16; o; o >>= 1) lm = fmaxf(lm, __shfl_xor_sync(0xffffffffu, lm, o));
    if ((tid & 31) == 0) red[tid >> 5] = lm;
    __syncthreads();
    if (tid == 0) {
        float m = red[0];
#pragma unroll
        for (int i = 1; i < 8; i++) m = fmaxf(m, red[i]);
        sM = m;
    }
    __syncthreads();
    float m = sM;

    float ls = 0.f;
    for (int t = tid; t < k; t += 256) {
        float e = __expf(sw[t] - m);
        sw[t] = e;
        ls += e;
    }
#pragma unroll
    for (int o = 16; o; o >>= 1) ls += __shfl_xor_sync(0xffffffffu, ls, o);
    if ((tid & 31) == 0) red[tid >> 5] = ls;
    __syncthreads();
    if (tid == 0) {
        float z = 0.f;
#pragma unroll
        for (int i = 0; i < 8; i++) z += red[i];
        sZ = z;
    }
    __syncthreads();
    float invZ = 1.0f / sZ;

    // aggregation: 4 groups of 64 threads, float4 per thread, edges strided by 4
    int grp = tid >> 6;
    int gl  = tid & 63;
    float4 acc = make_float4(0.f, 0.f, 0.f, 0.f);
#pragma unroll 2
    for (int t = grp; t < k; t += 4) {
        float w = sw[t];
        float4 hv = *(const float4*)(g_h + (size_t)scol[t] * OUT_F + gl * 4);
        acc.x += w * hv.x; acc.y += w * hv.y;
        acc.z += w * hv.z; acc.w += w * hv.w;
    }
    sred[grp][gl] = acc;
    __syncthreads();
    if (grp == 0) {
        float4 a0 = sred[0][gl], a1 = sred[1][gl], a2 = sred[2][gl], a3 = sred[3][gl];
        float4 r;
        r.x = (a0.x + a1.x + a2.x + a3.x) * invZ;
        r.y = (a0.y + a1.y + a2.y + a3.y) * invZ;
        r.z = (a0.z + a1.z + a2.z + a3.z) * invZ;
        r.w = (a0.w + a1.w + a2.w + a3.w) * invZ;
        *(float4*)(out + (size_t)row * OUT_F + gl * 4) = r;
    }
}

// ---------------- launch ---------------------------------------------------
extern "C" void kernel_launch(void* const* d_in, const int* in_sizes, int n_in,
                              void* d_out, int out_size) {
    const float* x  = (const float*)d_in[0];
    const float* W  = (const float*)d_in[1];
    const float* b  = (const float*)d_in[2];
    const float* a  = (const float*)d_in[3];
    const void*  el = d_in[4];
    float* out = (float*)d_out;

    cudaFuncSetAttribute(gemm_mma_kernel,
                         cudaFuncAttributeMaxDynamicSharedMemorySize, SM_GEMM);

    init_kernel<<<(N_NODES + 255) / 256, 256>>>((const int*)el);

    int ncvt = (N_NODES * IN_F + OUT_F * IN_F) / 4;
    cvt_kernel<<<(ncvt + 255) / 256, 256>>>(x, W);

    dim3 ggrid((N_NODES + BM - 1) / BM, OUT_F / BN);   // (79, 2)
    gemm_mma_kernel<<<ggrid, 256, SM_GEMM>>>(b, a);

    count_kernel<<<(N_EDGES + 255) / 256, 256>>>(el);
    scan_kernel<<<1, 1024>>>();
    colmean_kernel<<<128, OUT_F>>>();
    fill_kernel<<<(N_EDGES + 255) / 256, 256>>>(el);

    row_kernel<<<N_NODES, 256>>>(out);
}

// round 7
// speedup vs baseline: 1.5347x; 1.0198x over previous
#include <cuda_runtime.h>
#include <cuda_bf16.h>
#include <math_constants.h>
#include <cstdint>

#define N_NODES 10000
#define N_EDGES 320000
#define IN_F    512
#define OUT_F   256
#define ALPHA   0.2f

// ---------------- scratch (device globals; no allocation allowed) ----------
__device__ float g_h[(size_t)N_NODES * OUT_F];
__device__ float g_s1[N_NODES];
__device__ float g_s2[N_NODES];
__device__ int   g_rowptr[N_NODES + 1];
__device__ int   g_cnt[N_NODES];
__device__ int   g_cur[N_NODES];
__device__ int   g_col[N_EDGES];
__device__ float g_val[N_EDGES];
__device__ float g_colmean[OUT_F];
__device__ int   g_is64;
__device__ int   g_hasempty;
__device__ __nv_bfloat16 g_xh[(size_t)N_NODES * IN_F];
__device__ __nv_bfloat16 g_xl[(size_t)N_NODES * IN_F];
__device__ __nv_bfloat16 g_wh[(size_t)OUT_F * IN_F];
__device__ __nv_bfloat16 g_wl[(size_t)OUT_F * IN_F];

// ---------------- small helpers --------------------------------------------
__device__ __forceinline__ void ldsm4(uint32_t* r, uint32_t addr) {
    asm volatile("ldmatrix.sync.aligned.m8n8.x4.shared.b16 {%0,%1,%2,%3}, [%4];"
                 : "=r"(r[0]), "=r"(r[1]), "=r"(r[2]), "=r"(r[3]) : "r"(addr));
}
__device__ __forceinline__ void mma16816(float* c, const uint32_t* A, uint32_t b0, uint32_t b1) {
    asm volatile("mma.sync.aligned.m16n8k16.row.col.f32.bf16.bf16.f32 "
                 "{%0,%1,%2,%3}, {%4,%5,%6,%7}, {%8,%9}, {%0,%1,%2,%3};"
                 : "+f"(c[0]), "+f"(c[1]), "+f"(c[2]), "+f"(c[3])
                 : "r"(A[0]), "r"(A[1]), "r"(A[2]), "r"(A[3]), "r"(b0), "r"(b1));
}
__device__ __forceinline__ void cpa16(uint32_t dst, const void* src) {
    asm volatile("cp.async.cg.shared.global [%0], [%1], 16;" :: "r"(dst), "l"(src));
}
__device__ __forceinline__ int clampN(int v) {
    return (v < 0) ? 0 : (v >= N_NODES ? N_NODES - 1 : v);
}
// decode 4 consecutive indices starting at base element boff (boff % 4 == 0)
__device__ __forceinline__ void edge4(const void* el, int boff, int* s) {
    if (g_is64) {
        longlong2 p0 = ((const longlong2*)el)[boff >> 1];
        longlong2 p1 = ((const longlong2*)el)[(boff >> 1) + 1];
        s[0] = clampN((int)p0.x); s[1] = clampN((int)p0.y);
        s[2] = clampN((int)p1.x); s[3] = clampN((int)p1.y);
    } else {
        int4 p = ((const int4*)el)[boff >> 2];
        s[0] = clampN(p.x); s[1] = clampN(p.y);
        s[2] = clampN(p.z); s[3] = clampN(p.w);
    }
}

// ---------------- init (+ dtype probe in block 0) ---------------------------
__global__ void init_kernel(const int* __restrict__ p) {
    int i = blockIdx.x * blockDim.x + threadIdx.x;
    if (i == 0) {
        int nz = 0;
#pragma unroll
        for (int j = 0; j < 64; j++) nz |= p[2 * j + 1];
        g_is64 = (nz == 0) ? 1 : 0;
        g_hasempty = 0;
    }
    if (i < N_NODES) { g_cnt[i] = 0; g_cur[i] = 0; g_s1[i] = 0.f; g_s2[i] = 0.f; }
    if (i < OUT_F)   { g_colmean[i] = 0.f; }
}

// ---------------- fp32 -> bf16 hi/lo split (X and W, 8 floats/thread) ------
__global__ void cvt_kernel(const float* __restrict__ X, const float* __restrict__ W) {
    const int nx8 = N_NODES * IN_F / 8;
    const int nw8 = OUT_F * IN_F / 8;
    int i = blockIdx.x * blockDim.x + threadIdx.x;
    if (i >= nx8 + nw8) return;
    const float* src;
    __nv_bfloat16 *hi, *lo;
    int j;
    if (i < nx8) { src = X; hi = g_xh; lo = g_xl; j = i; }
    else         { src = W; hi = g_wh; lo = g_wl; j = i - nx8; }
#pragma unroll
    for (int u = 0; u < 2; u++) {
        float4 v = ((const float4*)src)[2 * j + u];
        __nv_bfloat16 h0 = __float2bfloat16_rn(v.x), h1 = __float2bfloat16_rn(v.y);
        __nv_bfloat16 h2 = __float2bfloat16_rn(v.z), h3 = __float2bfloat16_rn(v.w);
        __nv_bfloat162 H0 = {h0, h1}, H1 = {h2, h3};
        __nv_bfloat162 L0 = {__float2bfloat16_rn(v.x - __bfloat162float(h0)),
                             __float2bfloat16_rn(v.y - __bfloat162float(h1))};
        __nv_bfloat162 L1 = {__float2bfloat16_rn(v.z - __bfloat162float(h2)),
                             __float2bfloat16_rn(v.w - __bfloat162float(h3))};
        ((__nv_bfloat162*)hi)[4 * j + 2 * u]     = H0;
        ((__nv_bfloat162*)hi)[4 * j + 2 * u + 1] = H1;
        ((__nv_bfloat162*)lo)[4 * j + 2 * u]     = L0;
        ((__nv_bfloat162*)lo)[4 * j + 2 * u + 1] = L1;
    }
}

// ---------------- tensor-core GEMM, cp.async double-buffered ---------------
#define BM 128
#define BN 128
#define KB 32
#define KST 40
#define STG_B (BM * KST * 2)
#define NC (IN_F / KB)
#define SM_GEMM (2 * 4 * STG_B)

__global__ void __launch_bounds__(256, 2) gemm_mma_kernel(
    const float* __restrict__ bias, const float* __restrict__ av)
{
    extern __shared__ char dsm[];
    const uint32_t smb = (uint32_t)__cvta_generic_to_shared(dsm);

    const int tid  = threadIdx.x;
    const int lane = tid & 31;
    const int wid  = tid >> 5;
    const int wm   = wid & 3;
    const int wn   = wid >> 2;
    const int bm   = blockIdx.x * BM;
    const int bn   = blockIdx.y * BN;

    float acc[2][8][4];
#pragma unroll
    for (int i = 0; i < 2; i++)
#pragma unroll
        for (int j = 0; j < 8; j++)
#pragma unroll
            for (int q = 0; q < 4; q++) acc[i][j][q] = 0.f;

    const int sr = tid >> 1;
    const int sh = (tid & 1) * 16;
    const int rowA = (bm + sr < N_NODES) ? bm + sr : N_NODES - 1;
    const __nv_bfloat16* xhp = g_xh + (size_t)rowA * IN_F + sh;
    const __nv_bfloat16* xlp = g_xl + (size_t)rowA * IN_F + sh;
    const __nv_bfloat16* whp = g_wh + (size_t)(bn + sr) * IN_F + sh;
    const __nv_bfloat16* wlp = g_wl + (size_t)(bn + sr) * IN_F + sh;
    const uint32_t sdst = (uint32_t)(sr * KST + sh) * 2;

    const uint32_t a_row = lane & 15, a_cb = (lane >> 4) * 8;
    const uint32_t b_row = (lane & 7) + ((lane & 16) ? 8 : 0);
    const uint32_t b_cb  = (lane & 8) ? 8 : 0;

#define PREFETCH(ch, st) do {                                     \
    const int _k0 = (ch) * KB;                                    \
    uint32_t _b = smb + (st) * 4 * STG_B + sdst;                  \
    cpa16(_b,                  xhp + _k0);                        \
    cpa16(_b + 16,             xhp + _k0 + 8);                    \
    cpa16(_b + STG_B,          xlp + _k0);                        \
    cpa16(_b + STG_B + 16,     xlp + _k0 + 8);                    \
    cpa16(_b + 2 * STG_B,      whp + _k0);                        \
    cpa16(_b + 2 * STG_B + 16, whp + _k0 + 8);                    \
    cpa16(_b + 3 * STG_B,      wlp + _k0);                        \
    cpa16(_b + 3 * STG_B + 16, wlp + _k0 + 8);                    \
    asm volatile("cp.async.commit_group;" ::: "memory");          \
} while (0)

    PREFETCH(0, 0);

    for (int ch = 0; ch < NC; ch++) {
        if (ch + 1 < NC) {
            PREFETCH(ch + 1, (ch + 1) & 1);
            asm volatile("cp.async.wait_group 1;" ::: "memory");
        } else {
            asm volatile("cp.async.wait_group 0;" ::: "memory");
        }
        __syncthreads();

        const uint32_t sAh_b = smb + (ch & 1) * 4 * STG_B;
        const uint32_t sAl_b = sAh_b + STG_B;
        const uint32_t sBh_b = sAh_b + 2 * STG_B;
        const uint32_t sBl_b = sAh_b + 3 * STG_B;

#pragma unroll
        for (int ks = 0; ks < KB; ks += 16) {
            uint32_t ah[2][4], al[2][4];
#pragma unroll
            for (int mi = 0; mi < 2; mi++) {
                uint32_t off = ((wm * 32 + mi * 16 + a_row) * KST + ks + a_cb) * 2;
                ldsm4(ah[mi], sAh_b + off);
                ldsm4(al[mi], sAl_b + off);
            }
#pragma unroll
            for (int g = 0; g < 4; g++) {
                uint32_t off = ((wn * 64 + g * 16 + b_row) * KST + ks + b_cb) * 2;
                uint32_t bh[4], bl[4];
                ldsm4(bh, sBh_b + off);
                ldsm4(bl, sBl_b + off);
#pragma unroll
                for (int mi = 0; mi < 2; mi++) {
                    mma16816(acc[mi][2 * g],     ah[mi], bh[0], bh[1]);
                    mma16816(acc[mi][2 * g + 1], ah[mi], bh[2], bh[3]);
                    mma16816(acc[mi][2 * g],     ah[mi], bl[0], bl[1]);
                    mma16816(acc[mi][2 * g + 1], ah[mi], bl[2], bl[3]);
                    mma16816(acc[mi][2 * g],     al[mi], bh[0], bh[1]);
                    mma16816(acc[mi][2 * g + 1], al[mi], bh[2], bh[3]);
                }
            }
        }
        __syncthreads();
    }
#undef PREFETCH

    const int q  = lane >> 2;
    const int qt = lane & 3;
#pragma unroll
    for (int mi = 0; mi < 2; mi++) {
#pragma unroll
        for (int half = 0; half < 2; half++) {
            int row = bm + wm * 32 + mi * 16 + half * 8 + q;
            bool vr = (row < N_NODES);
            float p1 = 0.f, p2 = 0.f;
#pragma unroll
            for (int ni = 0; ni < 8; ni++) {
                int col = bn + wn * 64 + ni * 8 + qt * 2;
                float v0 = acc[mi][ni][half * 2 + 0] + bias[col];
                float v1 = acc[mi][ni][half * 2 + 1] + bias[col + 1];
                if (vr) *(float2*)(g_h + (size_t)row * OUT_F + col) = make_float2(v0, v1);
                p1 += v0 * av[col]         + v1 * av[col + 1];
                p2 += v0 * av[OUT_F + col] + v1 * av[OUT_F + col + 1];
            }
            p1 += __shfl_xor_sync(0xffffffffu, p1, 1);
            p1 += __shfl_xor_sync(0xffffffffu, p1, 2);
            p2 += __shfl_xor_sync(0xffffffffu, p2, 1);
            p2 += __shfl_xor_sync(0xffffffffu, p2, 2);
            if (qt == 0 && vr) {
                atomicAdd(&g_s1[row], p1);
                atomicAdd(&g_s2[row], p2);
            }
        }
    }
}

// ---------------- column means (only if an empty row exists) ---------------
__global__ void colmean_kernel() {
    if (!g_hasempty) return;
    int c = threadIdx.x;
    float acc = 0.f;
    for (int r = blockIdx.x; r < N_NODES; r += gridDim.x)
        acc += g_h[(size_t)r * OUT_F + c];
    atomicAdd(&g_colmean[c], acc);
}

// ---------------- CSR build (4 edges/thread) -------------------------------
__global__ void count_kernel(const void* __restrict__ el) {
    int e0 = (blockIdx.x * blockDim.x + threadIdx.x) * 4;
    if (e0 >= N_EDGES) return;
    int s[4];
    edge4(el, e0, s);
#pragma unroll
    for (int u = 0; u < 4; u++) atomicAdd(&g_cnt[s[u]], 1);
}

__global__ void scan_kernel() {
    __shared__ int ss[1024];
    int t = threadIdx.x;
    const int CH = (N_NODES + 1023) / 1024;
    int base = t * CH;
    int s = 0;
    int empty = 0;
    for (int i = 0; i < CH; i++) {
        int idx = base + i;
        if (idx < N_NODES) {
            int c = g_cnt[idx];
            s += c;
            empty |= (c == 0);
        }
    }
    if (empty) g_hasempty = 1;
    ss[t] = s;
    __syncthreads();
    for (int off = 1; off < 1024; off <<= 1) {
        int v = (t >= off) ? ss[t - off] : 0;
        __syncthreads();
        ss[t] += v;
        __syncthreads();
    }
    int run = ss[t] - s;
    for (int i = 0; i < CH; i++) {
        int idx = base + i;
        if (idx < N_NODES) { g_rowptr[idx] = run; run += g_cnt[idx]; }
    }
    if (t == 1023) g_rowptr[N_NODES] = run;
}

__global__ void fill_kernel(const void* __restrict__ el) {
    int e0 = (blockIdx.x * blockDim.x + threadIdx.x) * 4;
    if (e0 >= N_EDGES) return;
    int s[4], t4[4];
    edge4(el, e0, s);
    // tgt array starts at element N_EDGES (alignment holds: N_EDGES % 4 == 0)
    if (g_is64) {
        const longlong2* tp = (const longlong2*)((const long long*)el + N_EDGES);
        longlong2 p0 = tp[e0 >> 1], p1 = tp[(e0 >> 1) + 1];
        t4[0] = clampN((int)p0.x); t4[1] = clampN((int)p0.y);
        t4[2] = clampN((int)p1.x); t4[3] = clampN((int)p1.y);
    } else {
        const int4* tp = (const int4*)((const int*)el + N_EDGES);
        int4 p = tp[e0 >> 2];
        t4[0] = clampN(p.x); t4[1] = clampN(p.y);
        t4[2] = clampN(p.z); t4[3] = clampN(p.w);
    }
#pragma unroll
    for (int u = 0; u < 4; u++) {
        float sc = g_s1[s[u]] + g_s2[t4[u]];
        float v  = sc > 0.f ? sc : ALPHA * sc;
        int pos = g_rowptr[s[u]] + atomicAdd(&g_cur[s[u]], 1);
        if (pos < N_EDGES) { g_col[pos] = t4[u]; g_val[pos] = v; }
    }
}

// ---------------- per-row: dedup + softmax + aggregation -------------------
#define MAXK 512

__global__ void __launch_bounds__(256) row_kernel(float* __restrict__ out) {
    int row = blockIdx.x;
    int tid = threadIdx.x;
    int beg = g_rowptr[row];
    int k   = g_rowptr[row + 1] - beg;

    if (k == 0) {
        out[(size_t)row * OUT_F + tid] = g_colmean[tid] * (1.0f / N_NODES);
        return;
    }
    if (k > MAXK) k = MAXK;

    __shared__ int    scol[MAXK];
    __shared__ float  sval[MAXK];
    __shared__ float  sw[MAXK];
    __shared__ float  red[8];
    __shared__ float  sM, sZ;
    __shared__ float4 sred[4][64];

    for (int t = tid; t < k; t += 256) {
        scol[t] = g_col[beg + t];
        sval[t] = g_val[beg + t];
    }
    __syncthreads();

    for (int t = tid; t < k; t += 256) {
        int c = scol[t];
        bool owner = true;
        for (int j = 0; j < t; j++)
            if (scol[j] == c) { owner = false; break; }
        float v;
        if (owner) {
            v = sval[t];
            for (int j = t + 1; j < k; j++)
                if (scol[j] == c) v += sval[j];
        } else {
            v = -CUDART_INF_F;
        }
        sw[t] = v;
    }
    __syncthreads();

    float lm = -CUDART_INF_F;
    for (int t = tid; t < k; t += 256) lm = fmaxf(lm, sw[t]);
#pragma unroll
    for (int o = 16; o; o >>= 1) lm = fmaxf(lm, __shfl_xor_sync(0xffffffffu, lm, o));
    if ((tid & 31) == 0) red[tid >> 5] = lm;
    __syncthreads();
    if (tid == 0) {
        float m = red[0];
#pragma unroll
        for (int i = 1; i < 8; i++) m = fmaxf(m, red[i]);
        sM = m;
    }
    __syncthreads();
    float m = sM;

    float ls = 0.f;
    for (int t = tid; t < k; t += 256) {
        float e = __expf(sw[t] - m);
        sw[t] = e;
        ls += e;
    }
#pragma unroll
    for (int o = 16; o; o >>= 1) ls += __shfl_xor_sync(0xffffffffu, ls, o);
    if ((tid & 31) == 0) red[tid >> 5] = ls;
    __syncthreads();
    if (tid == 0) {
        float z = 0.f;
#pragma unroll
        for (int i = 0; i < 8; i++) z += red[i];
        sZ = z;
    }
    __syncthreads();
    float invZ = 1.0f / sZ;

    int grp = tid >> 6;
    int gl  = tid & 63;
    float4 acc = make_float4(0.f, 0.f, 0.f, 0.f);
#pragma unroll 4
    for (int t = grp; t < k; t += 4) {
        float w = sw[t];
        float4 hv = *(const float4*)(g_h + (size_t)scol[t] * OUT_F + gl * 4);
        acc.x += w * hv.x; acc.y += w * hv.y;
        acc.z += w * hv.z; acc.w += w * hv.w;
    }
    sred[grp][gl] = acc;
    __syncthreads();
    if (grp == 0) {
        float4 a0 = sred[0][gl], a1 = sred[1][gl], a2 = sred[2][gl], a3 = sred[3][gl];
        float4 r;
        r.x = (a0.x + a1.x + a2.x + a3.x) * invZ;
        r.y = (a0.y + a1.y + a2.y + a3.y) * invZ;
        r.z = (a0.z + a1.z + a2.z + a3.z) * invZ;
        r.w = (a0.w + a1.w + a2.w + a3.w) * invZ;
        *(float4*)(out + (size_t)row * OUT_F + gl * 4) = r;
    }
}

// ---------------- launch (fork edge chain onto side stream) ----------------
extern "C" void kernel_launch(void* const* d_in, const int* in_sizes, int n_in,
                              void* d_out, int out_size) {
    const float* x  = (const float*)d_in[0];
    const float* W  = (const float*)d_in[1];
    const float* b  = (const float*)d_in[2];
    const float* a  = (const float*)d_in[3];
    const void*  el = d_in[4];
    float* out = (float*)d_out;

    static cudaStream_t s_side = nullptr;
    static cudaEvent_t  ev_fork = nullptr, ev_scan = nullptr;
    static bool s_init = false;
    if (!s_init) {
        cudaStreamCreateWithFlags(&s_side, cudaStreamNonBlocking);
        cudaEventCreateWithFlags(&ev_fork, cudaEventDisableTiming);
        cudaEventCreateWithFlags(&ev_scan, cudaEventDisableTiming);
        cudaFuncSetAttribute(gemm_mma_kernel,
                             cudaFuncAttributeMaxDynamicSharedMemorySize, SM_GEMM);
        s_init = true;
    }

    init_kernel<<<(N_NODES + 255) / 256, 256>>>((const int*)el);
    cudaEventRecord(ev_fork, 0);

    // side stream: edge counting + scan (independent of GEMM chain)
    cudaStreamWaitEvent(s_side, ev_fork, 0);
    count_kernel<<<(N_EDGES / 4 + 255) / 256, 256, 0, s_side>>>(el);
    scan_kernel<<<1, 1024, 0, s_side>>>();
    cudaEventRecord(ev_scan, s_side);

    // main stream: convert + GEMM (+ fused s1/s2)
    int ncvt = (N_NODES * IN_F + OUT_F * IN_F) / 8;
    cvt_kernel<<<(ncvt + 255) / 256, 256>>>(x, W);
    dim3 ggrid((N_NODES + BM - 1) / BM, OUT_F / BN);
    gemm_mma_kernel<<<ggrid, 256, SM_GEMM>>>(b, a);

    // join: fill needs rowptr (side) + s1/s2 (main)
    cudaStreamWaitEvent(0, ev_scan, 0);
    fill_kernel<<<(N_EDGES / 4 + 255) / 256, 256>>>(el);
    colmean_kernel<<<128, OUT_F>>>();
    row_kernel<<<N_NODES, 256>>>(out);
}

// round 8
// speedup vs baseline: 1.6489x; 1.0745x over previous
#include <cuda_runtime.h>
#include <cuda_fp16.h>
#include <math_constants.h>
#include <cstdint>

#define N_NODES 10000
#define N_EDGES 320000
#define IN_F    512
#define OUT_F   256
#define ALPHA   0.2f

// ---------------- scratch (device globals; no allocation allowed) ----------
__device__ float g_h[(size_t)N_NODES * OUT_F];
__device__ float g_s1[N_NODES];
__device__ float g_s2[N_NODES];
__device__ int   g_rowptr[N_NODES + 1];
__device__ int   g_cnt[N_NODES];
__device__ int   g_cur[N_NODES];
__device__ int   g_col[N_EDGES];
__device__ float g_val[N_EDGES];
__device__ float g_colmean[OUT_F];
__device__ int   g_is64;
__device__ int   g_hasempty;
__device__ __half g_xh[(size_t)N_NODES * IN_F];
__device__ __half g_xl[(size_t)N_NODES * IN_F];
__device__ __half g_wh[(size_t)OUT_F * IN_F];

// ---------------- small helpers --------------------------------------------
__device__ __forceinline__ void ldsm4(uint32_t* r, uint32_t addr) {
    asm volatile("ldmatrix.sync.aligned.m8n8.x4.shared.b16 {%0,%1,%2,%3}, [%4];"
                 : "=r"(r[0]), "=r"(r[1]), "=r"(r[2]), "=r"(r[3]) : "r"(addr));
}
__device__ __forceinline__ void mma16816(float* c, const uint32_t* A, uint32_t b0, uint32_t b1) {
    asm volatile("mma.sync.aligned.m16n8k16.row.col.f32.f16.f16.f32 "
                 "{%0,%1,%2,%3}, {%4,%5,%6,%7}, {%8,%9}, {%0,%1,%2,%3};"
                 : "+f"(c[0]), "+f"(c[1]), "+f"(c[2]), "+f"(c[3])
                 : "r"(A[0]), "r"(A[1]), "r"(A[2]), "r"(A[3]), "r"(b0), "r"(b1));
}
__device__ __forceinline__ void cpa16(uint32_t dst, const void* src) {
    asm volatile("cp.async.cg.shared.global [%0], [%1], 16;" :: "r"(dst), "l"(src));
}
__device__ __forceinline__ int clampN(int v) {
    return (v < 0) ? 0 : (v >= N_NODES ? N_NODES - 1 : v);
}
__device__ __forceinline__ void edge4(const void* el, int boff, int* s) {
    if (g_is64) {
        longlong2 p0 = ((const longlong2*)el)[boff >> 1];
        longlong2 p1 = ((const longlong2*)el)[(boff >> 1) + 1];
        s[0] = clampN((int)p0.x); s[1] = clampN((int)p0.y);
        s[2] = clampN((int)p1.x); s[3] = clampN((int)p1.y);
    } else {
        int4 p = ((const int4*)el)[boff >> 2];
        s[0] = clampN(p.x); s[1] = clampN(p.y);
        s[2] = clampN(p.z); s[3] = clampN(p.w);
    }
}

// ---------------- init (+ dtype probe in block 0) ---------------------------
__global__ void init_kernel(const int* __restrict__ p) {
    int i = blockIdx.x * blockDim.x + threadIdx.x;
    if (i == 0) {
        int nz = 0;
#pragma unroll
        for (int j = 0; j < 64; j++) nz |= p[2 * j + 1];
        g_is64 = (nz == 0) ? 1 : 0;
        g_hasempty = 0;
    }
    if (i < N_NODES) { g_cnt[i] = 0; g_cur[i] = 0; g_s1[i] = 0.f; g_s2[i] = 0.f; }
    if (i < OUT_F)   { g_colmean[i] = 0.f; }
}

// ---------------- fp32 -> fp16 (X hi/lo split; W hi only) ------------------
__global__ void cvt_kernel(const float* __restrict__ X, const float* __restrict__ W) {
    const int nx8 = N_NODES * IN_F / 8;
    const int nw8 = OUT_F * IN_F / 8;
    int i = blockIdx.x * blockDim.x + threadIdx.x;
    if (i >= nx8 + nw8) return;
    if (i < nx8) {
#pragma unroll
        for (int u = 0; u < 2; u++) {
            float4 v = ((const float4*)X)[2 * i + u];
            __half h0 = __float2half_rn(v.x), h1 = __float2half_rn(v.y);
            __half h2 = __float2half_rn(v.z), h3 = __float2half_rn(v.w);
            __half2 H0 = {h0, h1}, H1 = {h2, h3};
            __half2 L0 = {__float2half_rn(v.x - __half2float(h0)),
                          __float2half_rn(v.y - __half2float(h1))};
            __half2 L1 = {__float2half_rn(v.z - __half2float(h2)),
                          __float2half_rn(v.w - __half2float(h3))};
            ((__half2*)g_xh)[4 * i + 2 * u]     = H0;
            ((__half2*)g_xh)[4 * i + 2 * u + 1] = H1;
            ((__half2*)g_xl)[4 * i + 2 * u]     = L0;
            ((__half2*)g_xl)[4 * i + 2 * u + 1] = L1;
        }
    } else {
        int j = i - nx8;
#pragma unroll
        for (int u = 0; u < 2; u++) {
            float4 v = ((const float4*)W)[2 * j + u];
            __half2 H0 = {__float2half_rn(v.x), __float2half_rn(v.y)};
            __half2 H1 = {__float2half_rn(v.z), __float2half_rn(v.w)};
            ((__half2*)g_wh)[4 * j + 2 * u]     = H0;
            ((__half2*)g_wh)[4 * j + 2 * u + 1] = H1;
        }
    }
}

// ---------------- tensor-core GEMM, fp16 2-term, 3-stage cp.async ----------
#define BM 128
#define BN 128
#define KB 32
#define KST 40
#define STG_B (BM * KST * 2)        // 10240 bytes per array per stage
#define NC (IN_F / KB)              // 16
#define NARR 3                      // Ah, Al, Bh
#define SM_GEMM (3 * NARR * STG_B)  // 92160

__global__ void __launch_bounds__(256, 2) gemm_mma_kernel(
    const float* __restrict__ bias, const float* __restrict__ av)
{
    extern __shared__ char dsm[];
    const uint32_t smb = (uint32_t)__cvta_generic_to_shared(dsm);

    const int tid  = threadIdx.x;
    const int lane = tid & 31;
    const int wid  = tid >> 5;
    const int wm   = wid & 3;
    const int wn   = wid >> 2;
    const int bm   = blockIdx.x * BM;
    const int bn   = blockIdx.y * BN;

    float acc[2][8][4];
#pragma unroll
    for (int i = 0; i < 2; i++)
#pragma unroll
        for (int j = 0; j < 8; j++)
#pragma unroll
            for (int q = 0; q < 4; q++) acc[i][j][q] = 0.f;

    const int sr = tid >> 1;
    const int sh = (tid & 1) * 16;
    const int rowA = (bm + sr < N_NODES) ? bm + sr : N_NODES - 1;
    const __half* xhp = g_xh + (size_t)rowA * IN_F + sh;
    const __half* xlp = g_xl + (size_t)rowA * IN_F + sh;
    const __half* whp = g_wh + (size_t)(bn + sr) * IN_F + sh;
    const uint32_t sdst = (uint32_t)(sr * KST + sh) * 2;

    const uint32_t a_row = lane & 15, a_cb = (lane >> 4) * 8;
    const uint32_t b_row = (lane & 7) + ((lane & 16) ? 8 : 0);
    const uint32_t b_cb  = (lane & 8) ? 8 : 0;

#define PREFETCH(ch) do {                                         \
    const int _k0 = (ch) * KB;                                    \
    uint32_t _b = smb + ((ch) % 3) * NARR * STG_B + sdst;         \
    cpa16(_b,                  xhp + _k0);                        \
    cpa16(_b + 16,             xhp + _k0 + 8);                    \
    cpa16(_b + STG_B,          xlp + _k0);                        \
    cpa16(_b + STG_B + 16,     xlp + _k0 + 8);                    \
    cpa16(_b + 2 * STG_B,      whp + _k0);                        \
    cpa16(_b + 2 * STG_B + 16, whp + _k0 + 8);                    \
    asm volatile("cp.async.commit_group;" ::: "memory");          \
} while (0)

    PREFETCH(0);
    PREFETCH(1);

    for (int ch = 0; ch < NC; ch++) {
        if (ch + 2 < NC) {
            PREFETCH(ch + 2);
            asm volatile("cp.async.wait_group 2;" ::: "memory");
        } else if (ch + 1 < NC) {
            asm volatile("cp.async.wait_group 1;" ::: "memory");
        } else {
            asm volatile("cp.async.wait_group 0;" ::: "memory");
        }
        __syncthreads();

        const uint32_t sAh_b = smb + (ch % 3) * NARR * STG_B;
        const uint32_t sAl_b = sAh_b + STG_B;
        const uint32_t sBh_b = sAh_b + 2 * STG_B;

#pragma unroll
        for (int ks = 0; ks < KB; ks += 16) {
            uint32_t ah[2][4], al[2][4];
#pragma unroll
            for (int mi = 0; mi < 2; mi++) {
                uint32_t off = ((wm * 32 + mi * 16 + a_row) * KST + ks + a_cb) * 2;
                ldsm4(ah[mi], sAh_b + off);
                ldsm4(al[mi], sAl_b + off);
            }
#pragma unroll
            for (int g = 0; g < 4; g++) {
                uint32_t off = ((wn * 64 + g * 16 + b_row) * KST + ks + b_cb) * 2;
                uint32_t bh[4];
                ldsm4(bh, sBh_b + off);
#pragma unroll
                for (int mi = 0; mi < 2; mi++) {
                    mma16816(acc[mi][2 * g],     ah[mi], bh[0], bh[1]);
                    mma16816(acc[mi][2 * g + 1], ah[mi], bh[2], bh[3]);
                    mma16816(acc[mi][2 * g],     al[mi], bh[0], bh[1]);
                    mma16816(acc[mi][2 * g + 1], al[mi], bh[2], bh[3]);
                }
            }
        }
        __syncthreads();
    }
#undef PREFETCH

    const int q  = lane >> 2;
    const int qt = lane & 3;
#pragma unroll
    for (int mi = 0; mi < 2; mi++) {
#pragma unroll
        for (int half = 0; half < 2; half++) {
            int row = bm + wm * 32 + mi * 16 + half * 8 + q;
            bool vr = (row < N_NODES);
            float p1 = 0.f, p2 = 0.f;
#pragma unroll
            for (int ni = 0; ni < 8; ni++) {
                int col = bn + wn * 64 + ni * 8 + qt * 2;
                float v0 = acc[mi][ni][half * 2 + 0] + bias[col];
                float v1 = acc[mi][ni][half * 2 + 1] + bias[col + 1];
                if (vr) *(float2*)(g_h + (size_t)row * OUT_F + col) = make_float2(v0, v1);
                p1 += v0 * av[col]         + v1 * av[col + 1];
                p2 += v0 * av[OUT_F + col] + v1 * av[OUT_F + col + 1];
            }
            p1 += __shfl_xor_sync(0xffffffffu, p1, 1);
            p1 += __shfl_xor_sync(0xffffffffu, p1, 2);
            p2 += __shfl_xor_sync(0xffffffffu, p2, 1);
            p2 += __shfl_xor_sync(0xffffffffu, p2, 2);
            if (qt == 0 && vr) {
                atomicAdd(&g_s1[row], p1);
                atomicAdd(&g_s2[row], p2);
            }
        }
    }
}

// ---------------- column means (only if an empty row exists) ---------------
__global__ void colmean_kernel() {
    if (!g_hasempty) return;
    int c = threadIdx.x;
    float acc = 0.f;
    for (int r = blockIdx.x; r < N_NODES; r += gridDim.x)
        acc += g_h[(size_t)r * OUT_F + c];
    atomicAdd(&g_colmean[c], acc);
}

// ---------------- CSR build (4 edges/thread) -------------------------------
__global__ void count_kernel(const void* __restrict__ el) {
    int e0 = (blockIdx.x * blockDim.x + threadIdx.x) * 4;
    if (e0 >= N_EDGES) return;
    int s[4];
    edge4(el, e0, s);
#pragma unroll
    for (int u = 0; u < 4; u++) atomicAdd(&g_cnt[s[u]], 1);
}

__global__ void scan_kernel() {
    __shared__ int ss[1024];
    int t = threadIdx.x;
    const int CH = (N_NODES + 1023) / 1024;
    int base = t * CH;
    int s = 0;
    int empty = 0;
    for (int i = 0; i < CH; i++) {
        int idx = base + i;
        if (idx < N_NODES) {
            int c = g_cnt[idx];
            s += c;
            empty |= (c == 0);
        }
    }
    if (empty) g_hasempty = 1;
    ss[t] = s;
    __syncthreads();
    for (int off = 1; off < 1024; off <<= 1) {
        int v = (t >= off) ? ss[t - off] : 0;
        __syncthreads();
        ss[t] += v;
        __syncthreads();
    }
    int run = ss[t] - s;
    for (int i = 0; i < CH; i++) {
        int idx = base + i;
        if (idx < N_NODES) { g_rowptr[idx] = run; run += g_cnt[idx]; }
    }
    if (t == 1023) g_rowptr[N_NODES] = run;
}

__global__ void fill_kernel(const void* __restrict__ el) {
    int e0 = (blockIdx.x * blockDim.x + threadIdx.x) * 4;
    if (e0 >= N_EDGES) return;
    int s[4], t4[4];
    edge4(el, e0, s);
    if (g_is64) {
        const longlong2* tp = (const longlong2*)((const long long*)el + N_EDGES);
        longlong2 p0 = tp[e0 >> 1], p1 = tp[(e0 >> 1) + 1];
        t4[0] = clampN((int)p0.x); t4[1] = clampN((int)p0.y);
        t4[2] = clampN((int)p1.x); t4[3] = clampN((int)p1.y);
    } else {
        const int4* tp = (const int4*)((const int*)el + N_EDGES);
        int4 p = tp[e0 >> 2];
        t4[0] = clampN(p.x); t4[1] = clampN(p.y);
        t4[2] = clampN(p.z); t4[3] = clampN(p.w);
    }
#pragma unroll
    for (int u = 0; u < 4; u++) {
        float sc = g_s1[s[u]] + g_s2[t4[u]];
        float v  = sc > 0.f ? sc : ALPHA * sc;
        int pos = g_rowptr[s[u]] + atomicAdd(&g_cur[s[u]], 1);
        if (pos < N_EDGES) { g_col[pos] = t4[u]; g_val[pos] = v; }
    }
}

// ---------------- per-row: dedup + softmax + aggregation -------------------
#define MAXK 512

__global__ void __launch_bounds__(256) row_kernel(float* __restrict__ out) {
    int row = blockIdx.x;
    int tid = threadIdx.x;
    int beg = g_rowptr[row];
    int k   = g_rowptr[row + 1] - beg;

    if (k == 0) {
        out[(size_t)row * OUT_F + tid] = g_colmean[tid] * (1.0f / N_NODES);
        return;
    }
    if (k > MAXK) k = MAXK;

    __shared__ int    scol[MAXK];
    __shared__ float  sval[MAXK];
    __shared__ float  sw[MAXK];
    __shared__ float  red[8];
    __shared__ float  sM, sZ;
    __shared__ float4 sred[4][64];

    for (int t = tid; t < k; t += 256) {
        scol[t] = g_col[beg + t];
        sval[t] = g_val[beg + t];
    }
    __syncthreads();

    for (int t = tid; t < k; t += 256) {
        int c = scol[t];
        bool owner = true;
        for (int j = 0; j < t; j++)
            if (scol[j] == c) { owner = false; break; }
        float v;
        if (owner) {
            v = sval[t];
            for (int j = t + 1; j < k; j++)
                if (scol[j] == c) v += sval[j];
        } else {
            v = -CUDART_INF_F;
        }
        sw[t] = v;
    }
    __syncthreads();

    float lm = -CUDART_INF_F;
    for (int t = tid; t < k; t += 256) lm = fmaxf(lm, sw[t]);
#pragma unroll
    for (int o = 16; o; o >>= 1) lm = fmaxf(lm, __shfl_xor_sync(0xffffffffu, lm, o));
    if ((tid & 31) == 0) red[tid >> 5] = lm;
    __syncthreads();
    if (tid == 0) {
        float m = red[0];
#pragma unroll
        for (int i = 1; i < 8; i++) m = fmaxf(m, red[i]);
        sM = m;
    }
    __syncthreads();
    float m = sM;

    float ls = 0.f;
    for (int t = tid; t < k; t += 256) {
        float e = __expf(sw[t] - m);
        sw[t] = e;
        ls += e;
    }
#pragma unroll
    for (int o = 16; o; o >>= 1) ls += __shfl_xor_sync(0xffffffffu, ls, o);
    if ((tid & 31) == 0) red[tid >> 5] = ls;
    __syncthreads();
    if (tid == 0) {
        float z = 0.f;
#pragma unroll
        for (int i = 0; i < 8; i++) z += red[i];
        sZ = z;
    }
    __syncthreads();
    float invZ = 1.0f / sZ;

    int grp = tid >> 6;
    int gl  = tid & 63;
    float4 acc = make_float4(0.f, 0.f, 0.f, 0.f);
#pragma unroll 8
    for (int t = grp; t < k; t += 4) {
        float w = sw[t];
        float4 hv = *(const float4*)(g_h + (size_t)scol[t] * OUT_F + gl * 4);
        acc.x += w * hv.x; acc.y += w * hv.y;
        acc.z += w * hv.z; acc.w += w * hv.w;
    }
    sred[grp][gl] = acc;
    __syncthreads();
    if (grp == 0) {
        float4 a0 = sred[0][gl], a1 = sred[1][gl], a2 = sred[2][gl], a3 = sred[3][gl];
        float4 r;
        r.x = (a0.x + a1.x + a2.x + a3.x) * invZ;
        r.y = (a0.y + a1.y + a2.y + a3.y) * invZ;
        r.z = (a0.z + a1.z + a2.z + a3.z) * invZ;
        r.w = (a0.w + a1.w + a2.w + a3.w) * invZ;
        *(float4*)(out + (size_t)row * OUT_F + gl * 4) = r;
    }
}

// ---------------- launch (fork edge chain onto side stream) ----------------
extern "C" void kernel_launch(void* const* d_in, const int* in_sizes, int n_in,
                              void* d_out, int out_size) {
    const float* x  = (const float*)d_in[0];
    const float* W  = (const float*)d_in[1];
    const float* b  = (const float*)d_in[2];
    const float* a  = (const float*)d_in[3];
    const void*  el = d_in[4];
    float* out = (float*)d_out;

    static cudaStream_t s_side = nullptr;
    static cudaEvent_t  ev_fork = nullptr, ev_scan = nullptr;
    static bool s_init = false;
    if (!s_init) {
        cudaStreamCreateWithFlags(&s_side, cudaStreamNonBlocking);
        cudaEventCreateWithFlags(&ev_fork, cudaEventDisableTiming);
        cudaEventCreateWithFlags(&ev_scan, cudaEventDisableTiming);
        cudaFuncSetAttribute(gemm_mma_kernel,
                             cudaFuncAttributeMaxDynamicSharedMemorySize, SM_GEMM);
        s_init = true;
    }

    init_kernel<<<(N_NODES + 255) / 256, 256>>>((const int*)el);
    cudaEventRecord(ev_fork, 0);

    cudaStreamWaitEvent(s_side, ev_fork, 0);
    count_kernel<<<(N_EDGES / 4 + 255) / 256, 256, 0, s_side>>>(el);
    scan_kernel<<<1, 1024, 0, s_side>>>();
    cudaEventRecord(ev_scan, s_side);

    int ncvt = (N_NODES * IN_F + OUT_F * IN_F) / 8;
    cvt_kernel<<<(ncvt + 255) / 256, 256>>>(x, W);
    dim3 ggrid((N_NODES + BM - 1) / BM, OUT_F / BN);
    gemm_mma_kernel<<<ggrid, 256, SM_GEMM>>>(b, a);

    cudaStreamWaitEvent(0, ev_scan, 0);
    fill_kernel<<<(N_EDGES / 4 + 255) / 256, 256>>>(el);
    colmean_kernel<<<128, OUT_F>>>();
    row_kernel<<<N_NODES, 256>>>(out);
}